// round 15
// baseline (speedup 1.0000x reference)
#include <cuda_runtime.h>
#include <cuda_bf16.h>
#include <float.h>
#include <stdint.h>

#define NQ      2048
#define DIMS    128
#define MTRAIN  100000
#define KNB     16
#define NC      10
#define NSPLIT  9
#define SPLIT   11112
#define QTILE   128
#define NQT     (NQ/QTILE)     // 16
#define CHUNK   256
#define QCAP    96
#define NCAND   (NSPLIT*KNB)   // 144
#define T0      100.0f
#define NCTA    (NSPLIT*NQT)   // 144

// smem map (bytes)
#define SA_OFF  0                     // 32KB A tile
#define SB(s)   (32768 + (s)*65536)   // 2 x 64KB B tiles (256 rows x 256B)
#define T2_OFF  163840                // 2 x 256 floats
#define CNT_OFF 165888                // 256 ints
#define LV_OFF  166912                // 16 x 128 floats
#define LI_OFF  175104                // 16 x 128 ints
#define VMX_OFF 183296                // 128 floats
#define SMEM_TOTAL 183808

// padded so unguarded tail prefetches stay in-bounds (256-row chunks)
__device__ float g_t2[MTRAIN + 256];
__device__ float g_x2[NQ];
__device__ __nv_bfloat16 g_train_hi[(size_t)(MTRAIN + 256) * DIMS];
__device__ __nv_bfloat16 g_x_hi[NQ * DIMS];
__device__ float g_topd[NQ * NCAND];
__device__ int   g_topi[NQ * NCAND];
// global candidate queues: [cta][buf][query][slot]
__device__ float g_qv[(size_t)NCTA * 2 * QTILE * QCAP];
__device__ int   g_qi[(size_t)NCTA * 2 * QTILE * QCAP];

__device__ __forceinline__ uint32_t smem_u32(const void* p) {
    uint32_t a;
    asm("{ .reg .u64 t; cvta.to.shared.u64 t, %1; cvt.u32.u64 %0, t; }" : "=r"(a) : "l"(p));
    return a;
}
__device__ __forceinline__ void cpa16(uint32_t dst, const void* src) {
    asm volatile("cp.async.cg.shared.global [%0], [%1], 16;" :: "r"(dst), "l"(src));
}
#define CP_COMMIT() asm volatile("cp.async.commit_group;" ::: "memory")
#define CP_WAIT0()  asm volatile("cp.async.wait_group 0;" ::: "memory")

__device__ __forceinline__ uint32_t swz(uint32_t off) {
    return off ^ ((off >> 4) & 0x70u);
}
__device__ __forceinline__ uint32_t pkbf(__nv_bfloat16 a, __nv_bfloat16 b) {
    return (uint32_t)__bfloat16_as_ushort(a) | ((uint32_t)__bfloat16_as_ushort(b) << 16);
}

// -------- kernel 1: norms + bf16 hi --------
__global__ void prep_kernel(const float* __restrict__ x, const float* __restrict__ train) {
    int warp = (blockIdx.x * blockDim.x + threadIdx.x) >> 5;
    int lane = threadIdx.x & 31;
    if (warp >= MTRAIN + NQ) return;
    const float* src; __nv_bfloat16* dh; float* t2dst;
    if (warp < MTRAIN) {
        src = train + (size_t)warp * DIMS;
        dh = g_train_hi + (size_t)warp * DIMS;
        t2dst = g_t2 + warp;
    } else {
        int q = warp - MTRAIN;
        src = x + (size_t)q * DIMS;
        dh = g_x_hi + (size_t)q * DIMS;
        t2dst = g_x2 + q;
    }
    float4 v = ((const float4*)src)[lane];
    ((uint2*)dh)[lane] = make_uint2(pkbf(__float2bfloat16(v.x), __float2bfloat16(v.y)),
                                    pkbf(__float2bfloat16(v.z), __float2bfloat16(v.w)));
    float s = v.x*v.x + v.y*v.y + v.z*v.z + v.w*v.w;
    #pragma unroll
    for (int o = 16; o > 0; o >>= 1) s += __shfl_down_sync(0xffffffffu, s, o);
    if (lane == 0) *t2dst = s;
}

// per-query top-16 insert (scanner-owned, stride-128 layout)
__device__ __forceinline__ void topk_ins(float* lv, int* li, int t,
                                         float sc, int gc, float& vmax, int& maxslot) {
    lv[maxslot * 128 + t] = sc;
    li[maxslot * 128 + t] = gc;
    float nm = lv[t]; int np = 0;
    #pragma unroll
    for (int j = 1; j < 16; j++) {
        float tj = lv[j * 128 + t];
        if (tj > nm) { nm = tj; np = j; }
    }
    vmax = nm; maxslot = np;
}

// -------- kernel 2: bf16 HMMA approx GEMM, 256-row chunks, global queues --------
__global__ __launch_bounds__(256, 1) void knn_kernel() {
    extern __shared__ char sm[];
    const uint32_t sb = smem_u32(sm);
    float* t2r  = (float*)(sm + T2_OFF);
    int*   cnts = (int*)(sm + CNT_OFF);
    float* lv   = (float*)(sm + LV_OFF);
    int*   li   = (int*)(sm + LI_OFF);
    float* vmx  = (float*)(sm + VMX_OFF);

    const int tid = threadIdx.x;
    const int wid = tid >> 5;
    const int lane = tid & 31;
    const int split = blockIdx.x;
    const int qt    = blockIdx.y;
    const int cta   = qt * NSPLIT + split;
    const int split_start = split * SPLIT;
    const int split_end   = min(split_start + SPLIT, MTRAIN);
    const int nch = (split_end - split_start + CHUNK - 1) / CHUNK;

    const int m0 = (wid >> 2) * 64;
    const int n0 = (wid & 3) * 32;
    const uint32_t xa   = (uint32_t)(lane & 7) << 4;
    const uint32_t athr = (uint32_t)((lane & 15) * 256 + ((lane >> 4) & 1) * 16);
    const uint32_t bthr = (uint32_t)((lane & 7) * 256 + ((lane >> 4) & 1) * 2048
                                     + ((lane >> 3) & 1) * 16);
    const int tq = lane >> 2, tc = lane & 3;

    // prologue: A (2048 slots) + B(0) (4096 slots) + t2(0) (64 slots)
    #pragma unroll
    for (int i = 0; i < 8; i++) {
        int e = tid + i * 256;
        int row = e >> 4, c16 = e & 15;
        uint32_t off = swz((uint32_t)(row * 256 + c16 * 16));
        cpa16(sb + SA_OFF + off,
              (const char*)g_x_hi + (size_t)(qt * QTILE + row) * 256 + c16 * 16);
    }
    #pragma unroll
    for (int i = 0; i < 16; i++) {
        int e = tid + i * 256;
        int row = e >> 4, c16 = e & 15;
        uint32_t off = swz((uint32_t)(row * 256 + c16 * 16));
        cpa16(sb + SB(0) + off,
              (const char*)g_train_hi + (size_t)(split_start + row) * 256 + c16 * 16);
    }
    if (tid < 64) cpa16(sb + T2_OFF + tid * 16, (const char*)(g_t2 + split_start) + tid * 16);
    CP_COMMIT();

    if (tid < 128) {
        #pragma unroll
        for (int j = 0; j < 16; j++) { lv[j * 128 + tid] = FLT_MAX; li[j * 128 + tid] = 0; }
        vmx[tid] = FLT_MAX;
    }
    cnts[tid] = 0;                 // both buffers (256 counters)
    float vmax = FLT_MAX; int maxslot = 0;   // scanner state (tid<128)
    CP_WAIT0();
    __syncthreads();

    for (int ch = 0; ch < nch; ch++) {
        const int nx = ch + 1;
        const int s = ch & 1;
        const int cbuf = ch & 1;

        // prefetch B(ch+1) (4096 slots) + t2(ch+1)  (unguarded; arrays padded)
        if (nx < nch) {
            const int cbn = split_start + nx * CHUNK;
            #pragma unroll
            for (int i = 0; i < 16; i++) {
                int e = tid + i * 256;
                int row = e >> 4, c16 = e & 15;
                cpa16(sb + SB(nx & 1) + swz((uint32_t)(row * 256 + c16 * 16)),
                      (const char*)g_train_hi + (size_t)(cbn + row) * 256 + c16 * 16);
            }
            if (tid < 64) cpa16(sb + T2_OFF + (nx & 1) * 1024 + tid * 16,
                                (const char*)(g_t2 + cbn) + tid * 16);
            CP_COMMIT();
        }

        // ---- two n-halves: MMA + produce each ----
        #pragma unroll 1
        for (int h = 0; h < 2; h++) {
            const int cb = split_start + ch * CHUNK + h * 128;

            float acc[16][4];
            #pragma unroll
            for (int i = 0; i < 16; i++)
                #pragma unroll
                for (int j = 0; j < 4; j++) acc[i][j] = 0.f;

            const uint32_t sa = sb + SA_OFF;
            const uint32_t sbB = sb + SB(s) + h * 32768;

            #pragma unroll
            for (int kk = 0; kk < 8; kk++) {
                uint32_t a[4][4], b[4][2];
                #pragma unroll
                for (int i = 0; i < 4; i++) {
                    uint32_t off = (uint32_t)((m0 + i * 16) * 256) + athr + kk * 32;
                    asm volatile("ldmatrix.sync.aligned.m8n8.x4.shared.b16 {%0,%1,%2,%3}, [%4];"
                        : "=r"(a[i][0]), "=r"(a[i][1]), "=r"(a[i][2]), "=r"(a[i][3])
                        : "r"(sa + (off ^ xa)));
                }
                #pragma unroll
                for (int j2 = 0; j2 < 2; j2++) {
                    uint32_t off = (uint32_t)(n0 * 256 + j2 * 4096) + bthr + kk * 32;
                    asm volatile("ldmatrix.sync.aligned.m8n8.x4.shared.b16 {%0,%1,%2,%3}, [%4];"
                        : "=r"(b[j2*2][0]), "=r"(b[j2*2][1]), "=r"(b[j2*2+1][0]), "=r"(b[j2*2+1][1])
                        : "r"(sbB + (off ^ xa)));
                }
                #pragma unroll
                for (int i = 0; i < 4; i++)
                    #pragma unroll
                    for (int j = 0; j < 4; j++) {
                        float* d = acc[i * 4 + j];
                        asm volatile("mma.sync.aligned.m16n8k16.row.col.f32.bf16.bf16.f32 "
                            "{%0,%1,%2,%3}, {%4,%5,%6,%7}, {%8,%9}, {%0,%1,%2,%3};"
                            : "+f"(d[0]), "+f"(d[1]), "+f"(d[2]), "+f"(d[3])
                            : "r"(a[i][0]), "r"(a[i][1]), "r"(a[i][2]), "r"(a[i][3]),
                              "r"(b[j][0]), "r"(b[j][1]));
                    }
            }

            // produce: threshold-filter scores, append survivors to global queues
            {
                float thrA[4], thrB[4];
                #pragma unroll
                for (int i = 0; i < 4; i++) {
                    thrA[i] = fminf(vmx[m0 + i * 16 + tq], T0);
                    thrB[i] = fminf(vmx[m0 + i * 16 + tq + 8], T0);
                }
                const float* t2c = t2r + s * 256 + h * 128;
                const size_t qb_base = ((size_t)cta * 2 + cbuf) * QTILE;
                #pragma unroll
                for (int j = 0; j < 4; j++) {
                    int c2 = (n0 >> 1) + j * 4 + tc;
                    int c0 = 2 * c2;
                    float t20 = t2c[c0], t21 = t2c[c0 + 1];
                    int g0 = cb + c0, g1 = g0 + 1;
                    bool in0 = g0 < split_end, in1 = g1 < split_end;
                    #pragma unroll
                    for (int i = 0; i < 4; i++) {
                        const float* d = acc[i * 4 + j];
                        int qa = m0 + i * 16 + tq, qqb = qa + 8;
                        float s00 = fmaf(-2.f, d[0], t20);
                        float s01 = fmaf(-2.f, d[1], t21);
                        float s10 = fmaf(-2.f, d[2], t20);
                        float s11 = fmaf(-2.f, d[3], t21);
                        if (in0 && s00 < thrA[i]) {
                            int sl = atomicAdd(&cnts[cbuf * 128 + qa], 1);
                            if (sl < QCAP) {
                                size_t p = (qb_base + qa) * QCAP + sl;
                                g_qv[p] = s00; g_qi[p] = g0;
                            }
                        }
                        if (in1 && s01 < thrA[i]) {
                            int sl = atomicAdd(&cnts[cbuf * 128 + qa], 1);
                            if (sl < QCAP) {
                                size_t p = (qb_base + qa) * QCAP + sl;
                                g_qv[p] = s01; g_qi[p] = g1;
                            }
                        }
                        if (in0 && s10 < thrB[i]) {
                            int sl = atomicAdd(&cnts[cbuf * 128 + qqb], 1);
                            if (sl < QCAP) {
                                size_t p = (qb_base + qqb) * QCAP + sl;
                                g_qv[p] = s10; g_qi[p] = g0;
                            }
                        }
                        if (in1 && s11 < thrB[i]) {
                            int sl = atomicAdd(&cnts[cbuf * 128 + qqb], 1);
                            if (sl < QCAP) {
                                size_t p = (qb_base + qqb) * QCAP + sl;
                                g_qv[p] = s11; g_qi[p] = g1;
                            }
                        }
                    }
                }
            }
        }

        // ---- drain previous chunk's queue (scanner t owns query t) ----
        {
            const int pb = cbuf ^ 1;
            if (tid < 128) {
                int n = min(cnts[pb * 128 + tid], QCAP);
                const size_t base = (((size_t)cta * 2 + pb) * QTILE + tid) * QCAP;
                for (int k = 0; k < n; k++) {
                    float v = g_qv[base + k];
                    if (v < vmax) topk_ins(lv, li, tid, v, g_qi[base + k], vmax, maxslot);
                }
                cnts[pb * 128 + tid] = 0;
                vmx[tid] = vmax;
            }
        }
        CP_WAIT0();
        __syncthreads();
    }

    // ---- tail: drain last chunk's queue ----
    {
        const int pb = (nch - 1) & 1;
        if (tid < 128) {
            int n = min(cnts[pb * 128 + tid], QCAP);
            const size_t base = (((size_t)cta * 2 + pb) * QTILE + tid) * QCAP;
            for (int k = 0; k < n; k++) {
                float v = g_qv[base + k];
                if (v < vmax) topk_ins(lv, li, tid, v, g_qi[base + k], vmax, maxslot);
            }
        }
    }
    __syncthreads();

    // dump per-(query,split) top-16 approx candidates
    if (tid < 128) {
        int q = qt * QTILE + tid;
        int base = (q * NSPLIT + split) * KNB;
        #pragma unroll
        for (int j = 0; j < 16; j++) {
            g_topd[base + j] = lv[j * 128 + tid];
            g_topi[base + j] = li[j * 128 + tid];
        }
    }
}

// -------- kernel 3: merge 144 approx -> top-32 -> exact fp32 refine -> vote --------
__global__ void finalize_kernel(const float* __restrict__ x,
                                const float* __restrict__ train,
                                const int* __restrict__ labels,
                                float* __restrict__ pred_out,
                                float* __restrict__ proba_out) {
    __shared__ float xs[8][128];
    int warp = threadIdx.x >> 5, lane = threadIdx.x & 31;
    int q = blockIdx.x * 8 + warp;

    float cv[5]; int ci[5];
    const float* td = g_topd + (size_t)q * NCAND;
    const int*   ti = g_topi + (size_t)q * NCAND;
    #pragma unroll
    for (int t = 0; t < 5; t++) {
        int idx = lane + 32 * t;
        if (idx < NCAND) { cv[t] = td[idx]; ci[t] = ti[idx]; }
        else             { cv[t] = FLT_MAX; ci[t] = 0; }
    }

    // approx-top-32; winner of round r kept by lane r
    int myidx = 0;
    for (int r = 0; r < 32; r++) {
        float mv = cv[0]; int ms = 0;
        #pragma unroll
        for (int t = 1; t < 5; t++) if (cv[t] < mv) { mv = cv[t]; ms = t; }
        float rv = mv; int ridx = ci[0]; int rlane = lane;
        #pragma unroll
        for (int t = 0; t < 5; t++) if (t == ms) ridx = ci[t];
        #pragma unroll
        for (int o = 16; o > 0; o >>= 1) {
            float ov = __shfl_down_sync(0xffffffffu, rv, o);
            int   oi = __shfl_down_sync(0xffffffffu, ridx, o);
            int   ol = __shfl_down_sync(0xffffffffu, rlane, o);
            if (ov < rv) { rv = ov; ridx = oi; rlane = ol; }
        }
        ridx  = __shfl_sync(0xffffffffu, ridx, 0);
        rlane = __shfl_sync(0xffffffffu, rlane, 0);
        if (lane == r) myidx = ridx;
        #pragma unroll
        for (int t = 0; t < 5; t++)
            if (lane == rlane && t == ms) cv[t] = FLT_MAX;
    }

    // exact fp32 distance for my candidate
    ((float4*)xs[warp])[lane] = ((const float4*)(x + (size_t)q * DIMS))[lane];
    __syncwarp();
    const float4* t4 = (const float4*)(train + (size_t)myidx * DIMS);
    const float4* x4 = (const float4*)xs[warp];
    float dot = 0.f;
    #pragma unroll 8
    for (int i = 0; i < 32; i++) {
        float4 tv = t4[i], xv = x4[i];
        dot += xv.x*tv.x + xv.y*tv.y + xv.z*tv.z + xv.w*tv.w;
    }
    float d2 = g_x2[q] + g_t2[myidx] - 2.0f * dot;
    float myv = sqrtf(fmaxf(d2, 0.0f));
    int   lab = labels[myidx];

    // exact top-16 of 32 + weighted vote
    float proba[NC], pz[NC];
    #pragma unroll
    for (int c = 0; c < NC; c++) { proba[c] = 0.f; pz[c] = 0.f; }
    bool anyz = false;

    for (int r = 0; r < KNB; r++) {
        float rv = myv; int rlab = lab; int rlane = lane;
        #pragma unroll
        for (int o = 16; o > 0; o >>= 1) {
            float ov = __shfl_down_sync(0xffffffffu, rv, o);
            int   oi = __shfl_down_sync(0xffffffffu, rlab, o);
            int   ol = __shfl_down_sync(0xffffffffu, rlane, o);
            if (ov < rv) { rv = ov; rlab = oi; rlane = ol; }
        }
        rv    = __shfl_sync(0xffffffffu, rv, 0);
        rlab  = __shfl_sync(0xffffffffu, rlab, 0);
        rlane = __shfl_sync(0xffffffffu, rlane, 0);
        if (lane == rlane) myv = FLT_MAX;

        if (rv <= 0.0f) {
            anyz = true;
            #pragma unroll
            for (int c = 0; c < NC; c++) pz[c] += (rlab == c) ? 1.0f : 0.0f;
        } else {
            float w = 1.0f / rv;
            #pragma unroll
            for (int c = 0; c < NC; c++) proba[c] += (rlab == c) ? w : 0.0f;
        }
    }

    if (anyz) {
        #pragma unroll
        for (int c = 0; c < NC; c++) proba[c] = pz[c];
    }
    float ssum = 0.f;
    #pragma unroll
    for (int c = 0; c < NC; c++) ssum += proba[c];
    if (ssum == 0.f) ssum = 1.f;
    float inv = 1.f / ssum;

    int best = 0; float bv = proba[0];
    #pragma unroll
    for (int c = 1; c < NC; c++) if (proba[c] > bv) { bv = proba[c]; best = c; }

    if (lane == 0) {
        if (pred_out)  pred_out[q] = (float)best;
        if (proba_out) {
            #pragma unroll
            for (int c = 0; c < NC; c++) proba_out[q * NC + c] = proba[c] * inv;
        }
    }
}

// -------- launch --------
extern "C" void kernel_launch(void* const* d_in, const int* in_sizes, int n_in,
                              void* d_out, int out_size) {
    const float* x      = (const float*)d_in[0];
    const float* train  = (const float*)d_in[1];
    const int*   labels = (const int*)d_in[2];
    float* out = (float*)d_out;

    float* pred_out  = nullptr;
    float* proba_out = nullptr;
    if (out_size >= NQ * (NC + 1)) { pred_out = out; proba_out = out + NQ; }
    else if (out_size == NQ * NC)  { proba_out = out; }
    else                           { pred_out = out; }

    cudaFuncSetAttribute(knn_kernel, cudaFuncAttributeMaxDynamicSharedMemorySize, SMEM_TOTAL);

    prep_kernel<<<(MTRAIN + NQ + 7) / 8, 256>>>(x, train);
    knn_kernel<<<dim3(NSPLIT, NQT), 256, SMEM_TOTAL>>>();
    finalize_kernel<<<NQ / 8, 256>>>(x, train, labels, pred_out, proba_out);
}

// round 16
// speedup vs baseline: 1.2803x; 1.2803x over previous
#include <cuda_runtime.h>
#include <cuda_bf16.h>
#include <float.h>
#include <stdint.h>

#define NQ      2048
#define DIMS    128
#define MTRAIN  100000
#define KNB     16
#define NC      10
#define NSPLIT  9
#define SPLIT   11136          // 87*128: splits 0-7 chunk-aligned
#define QTILE   128
#define CHUNK   128
#define QCAP    48
#define NCAND   (NSPLIT*KNB)   // 144
#define T0      100.0f

// smem map (bytes)
#define SA_OFF  0                     // 32KB A tile
#define SB(s)   (32768 + (s)*32768)   // 2 x 32KB B tiles
#define T2_OFF  98304                 // 2 x 128 floats
#define QV_OFF  99328                 // 2 x 128 x 48 floats = 49152
#define QI_OFF  148480                // 49152
#define CNT_OFF 197632                // 256 ints
#define LV_OFF  198656                // 16 x 128 floats
#define LI_OFF  206848                // 16 x 128 ints
#define VMX_OFF 215040                // 128 floats
#define SMEM_TOTAL 215552

// padded; pad rows are POISONED (t2=1e30, train=0) so produce needs no bounds checks
__device__ float g_t2[MTRAIN + 128];
__device__ float g_x2[NQ];
__device__ __nv_bfloat16 g_train_hi[(size_t)(MTRAIN + 128) * DIMS];
__device__ __nv_bfloat16 g_x_hi[NQ * DIMS];
__device__ float g_topd[NQ * NCAND];
__device__ int   g_topi[NQ * NCAND];

__device__ __forceinline__ uint32_t smem_u32(const void* p) {
    uint32_t a;
    asm("{ .reg .u64 t; cvta.to.shared.u64 t, %1; cvt.u32.u64 %0, t; }" : "=r"(a) : "l"(p));
    return a;
}
__device__ __forceinline__ void cpa16(uint32_t dst, const void* src) {
    asm volatile("cp.async.cg.shared.global [%0], [%1], 16;" :: "r"(dst), "l"(src));
}
#define CP_COMMIT() asm volatile("cp.async.commit_group;" ::: "memory")
#define CP_WAIT0()  asm volatile("cp.async.wait_group 0;" ::: "memory")

__device__ __forceinline__ uint32_t swz(uint32_t off) {
    return off ^ ((off >> 4) & 0x70u);
}
__device__ __forceinline__ uint32_t pkbf(__nv_bfloat16 a, __nv_bfloat16 b) {
    return (uint32_t)__bfloat16_as_ushort(a) | ((uint32_t)__bfloat16_as_ushort(b) << 16);
}

// -------- kernel 1: norms + bf16 hi + poisoned pad --------
__global__ void prep_kernel(const float* __restrict__ x, const float* __restrict__ train) {
    int warp = (blockIdx.x * blockDim.x + threadIdx.x) >> 5;
    int lane = threadIdx.x & 31;
    if (warp >= MTRAIN + NQ + 128) return;

    if (warp >= MTRAIN + NQ) {                 // pad rows: poison
        int pr = warp - MTRAIN - NQ;
        ((uint2*)(g_train_hi + (size_t)(MTRAIN + pr) * DIMS))[lane] = make_uint2(0u, 0u);
        if (lane == 0) g_t2[MTRAIN + pr] = 1e30f;
        return;
    }

    const float* src; __nv_bfloat16* dh; float* t2dst;
    if (warp < MTRAIN) {
        src = train + (size_t)warp * DIMS;
        dh = g_train_hi + (size_t)warp * DIMS;
        t2dst = g_t2 + warp;
    } else {
        int q = warp - MTRAIN;
        src = x + (size_t)q * DIMS;
        dh = g_x_hi + (size_t)q * DIMS;
        t2dst = g_x2 + q;
    }
    float4 v = ((const float4*)src)[lane];
    ((uint2*)dh)[lane] = make_uint2(pkbf(__float2bfloat16(v.x), __float2bfloat16(v.y)),
                                    pkbf(__float2bfloat16(v.z), __float2bfloat16(v.w)));
    float s = v.x*v.x + v.y*v.y + v.z*v.z + v.w*v.w;
    #pragma unroll
    for (int o = 16; o > 0; o >>= 1) s += __shfl_down_sync(0xffffffffu, s, o);
    if (lane == 0) *t2dst = s;
}

// per-query top-16 insert (scanner-owned, stride-128 layout)
__device__ __forceinline__ void topk_ins(float* lv, int* li, int t,
                                         float sc, int gc, float& vmax, int& maxslot) {
    lv[maxslot * 128 + t] = sc;
    li[maxslot * 128 + t] = gc;
    float nm = lv[t]; int np = 0;
    #pragma unroll
    for (int j = 1; j < 16; j++) {
        float tj = lv[j * 128 + t];
        if (tj > nm) { nm = tj; np = j; }
    }
    vmax = nm; maxslot = np;
}

// -------- kernel 2: bf16 HMMA approx GEMM + threshold-filtered sparse top-16 --------
__global__ __launch_bounds__(256, 1) void knn_kernel() {
    extern __shared__ char sm[];
    const uint32_t sb = smem_u32(sm);
    float* t2r  = (float*)(sm + T2_OFF);
    float* qv   = (float*)(sm + QV_OFF);
    int*   qi   = (int*)(sm + QI_OFF);
    int*   cnts = (int*)(sm + CNT_OFF);
    float* lv   = (float*)(sm + LV_OFF);
    int*   li   = (int*)(sm + LI_OFF);
    float* vmx  = (float*)(sm + VMX_OFF);

    const int tid = threadIdx.x;
    const int wid = tid >> 5;
    const int lane = tid & 31;
    const int split = blockIdx.x;
    const int qt    = blockIdx.y;
    const int split_start = split * SPLIT;
    const int split_end   = min(split_start + SPLIT, MTRAIN);
    const int nch = (split_end - split_start + CHUNK - 1) / CHUNK;

    const int m0 = (wid >> 2) * 64;
    const int n0 = (wid & 3) * 32;
    const uint32_t xa   = (uint32_t)(lane & 7) << 4;
    const uint32_t athr = (uint32_t)((lane & 15) * 256 + ((lane >> 4) & 1) * 16);
    const uint32_t bthr = (uint32_t)((lane & 7) * 256 + ((lane >> 4) & 1) * 2048
                                     + ((lane >> 3) & 1) * 16);
    const int tq = lane >> 2, tc = lane & 3;

    // prologue: A + B(0) + t2(0)
    #pragma unroll
    for (int i = 0; i < 4; i++) {
        int e = tid + i * 256;
        int row = e >> 3, c16 = e & 7;
        uint32_t off0 = swz((uint32_t)(row * 256 + c16 * 16));
        uint32_t off1 = swz((uint32_t)(row * 256 + (c16 + 8) * 16));
        size_t gq = (size_t)(qt * QTILE + row) * 256;
        size_t gb = (size_t)(split_start + row) * 256;
        cpa16(sb + SA_OFF + off0, (const char*)g_x_hi + gq + c16 * 16);
        cpa16(sb + SA_OFF + off1, (const char*)g_x_hi + gq + (c16 + 8) * 16);
        cpa16(sb + SB(0) + off0, (const char*)g_train_hi + gb + c16 * 16);
        cpa16(sb + SB(0) + off1, (const char*)g_train_hi + gb + (c16 + 8) * 16);
    }
    if (tid < 32) cpa16(sb + T2_OFF + tid * 16, (const char*)(g_t2 + split_start) + tid * 16);
    CP_COMMIT();

    if (tid < 128) {
        #pragma unroll
        for (int j = 0; j < 16; j++) { lv[j * 128 + tid] = FLT_MAX; li[j * 128 + tid] = 0; }
        vmx[tid] = FLT_MAX;
    }
    cnts[tid] = 0;                 // both buffers (256 counters)
    float vmax = FLT_MAX; int maxslot = 0;   // scanner state (tid<128)
    CP_WAIT0();
    __syncthreads();

    for (int ch = 0; ch < nch; ch++) {
        const int cb = split_start + ch * CHUNK;
        const int nx = ch + 1;
        const int s = ch & 1;
        const int cbuf = ch & 1;

        // prefetch B(ch+1) + t2(ch+1)  (unguarded; arrays padded + poisoned)
        if (nx < nch) {
            const int cbn = split_start + nx * CHUNK;
            #pragma unroll
            for (int i = 0; i < 8; i++) {
                int e = tid + i * 256;
                int row = e >> 4, c16 = e & 15;
                cpa16(sb + SB(nx & 1) + swz((uint32_t)(row * 256 + c16 * 16)),
                      (const char*)g_train_hi + (size_t)(cbn + row) * 256 + c16 * 16);
            }
            if (tid < 32) cpa16(sb + T2_OFF + (nx & 1) * 512 + tid * 16,
                                (const char*)(g_t2 + cbn) + tid * 16);
            CP_COMMIT();
        }

        float acc[16][4];
        #pragma unroll
        for (int i = 0; i < 16; i++)
            #pragma unroll
            for (int j = 0; j < 4; j++) acc[i][j] = 0.f;

        const uint32_t sa = sb + SA_OFF, sbB = sb + SB(s);

        // MMA k-loop (R12-proven)
        #pragma unroll
        for (int kk = 0; kk < 8; kk++) {
            uint32_t a[4][4], b[4][2];
            #pragma unroll
            for (int i = 0; i < 4; i++) {
                uint32_t off = (uint32_t)((m0 + i * 16) * 256) + athr + kk * 32;
                asm volatile("ldmatrix.sync.aligned.m8n8.x4.shared.b16 {%0,%1,%2,%3}, [%4];"
                    : "=r"(a[i][0]), "=r"(a[i][1]), "=r"(a[i][2]), "=r"(a[i][3])
                    : "r"(sa + (off ^ xa)));
            }
            #pragma unroll
            for (int j2 = 0; j2 < 2; j2++) {
                uint32_t off = (uint32_t)(n0 * 256 + j2 * 4096) + bthr + kk * 32;
                asm volatile("ldmatrix.sync.aligned.m8n8.x4.shared.b16 {%0,%1,%2,%3}, [%4];"
                    : "=r"(b[j2*2][0]), "=r"(b[j2*2][1]), "=r"(b[j2*2+1][0]), "=r"(b[j2*2+1][1])
                    : "r"(sbB + (off ^ xa)));
            }
            #pragma unroll
            for (int i = 0; i < 4; i++)
                #pragma unroll
                for (int j = 0; j < 4; j++) {
                    float* d = acc[i * 4 + j];
                    asm volatile("mma.sync.aligned.m16n8k16.row.col.f32.bf16.bf16.f32 "
                        "{%0,%1,%2,%3}, {%4,%5,%6,%7}, {%8,%9}, {%0,%1,%2,%3};"
                        : "+f"(d[0]), "+f"(d[1]), "+f"(d[2]), "+f"(d[3])
                        : "r"(a[i][0]), "r"(a[i][1]), "r"(a[i][2]), "r"(a[i][3]),
                          "r"(b[j][0]), "r"(b[j][1]));
                }
        }

        // ---- produce: threshold-filter scores, append survivors (BRANCHLESS bounds) ----
        {
            float thrA[4], thrB[4];
            #pragma unroll
            for (int i = 0; i < 4; i++) {
                thrA[i] = fminf(vmx[m0 + i * 16 + tq], T0);
                thrB[i] = fminf(vmx[m0 + i * 16 + tq + 8], T0);
            }
            const float* t2c = t2r + (ch & 1) * 128;
            #pragma unroll
            for (int j = 0; j < 4; j++) {
                int c2 = (n0 >> 1) + j * 4 + tc;
                int c0 = 2 * c2;
                float t20 = t2c[c0], t21 = t2c[c0 + 1];
                int g0 = cb + c0, g1 = g0 + 1;
                #pragma unroll
                for (int i = 0; i < 4; i++) {
                    const float* d = acc[i * 4 + j];
                    int qa = m0 + i * 16 + tq, qb = qa + 8;
                    float s00 = fmaf(-2.f, d[0], t20);
                    float s01 = fmaf(-2.f, d[1], t21);
                    float s10 = fmaf(-2.f, d[2], t20);
                    float s11 = fmaf(-2.f, d[3], t21);
                    if (s00 < thrA[i]) {
                        int sl = atomicAdd(&cnts[cbuf * 128 + qa], 1);
                        if (sl < QCAP) { qv[(cbuf*128+qa)*QCAP+sl] = s00; qi[(cbuf*128+qa)*QCAP+sl] = g0; }
                    }
                    if (s01 < thrA[i]) {
                        int sl = atomicAdd(&cnts[cbuf * 128 + qa], 1);
                        if (sl < QCAP) { qv[(cbuf*128+qa)*QCAP+sl] = s01; qi[(cbuf*128+qa)*QCAP+sl] = g1; }
                    }
                    if (s10 < thrB[i]) {
                        int sl = atomicAdd(&cnts[cbuf * 128 + qb], 1);
                        if (sl < QCAP) { qv[(cbuf*128+qb)*QCAP+sl] = s10; qi[(cbuf*128+qb)*QCAP+sl] = g0; }
                    }
                    if (s11 < thrB[i]) {
                        int sl = atomicAdd(&cnts[cbuf * 128 + qb], 1);
                        if (sl < QCAP) { qv[(cbuf*128+qb)*QCAP+sl] = s11; qi[(cbuf*128+qb)*QCAP+sl] = g1; }
                    }
                }
            }
        }

        // ---- drain previous chunk's queue (scanner t owns query t) ----
        {
            const int pb = cbuf ^ 1;
            if (tid < 128) {
                int n = min(cnts[pb * 128 + tid], QCAP);
                const float* qvb = qv + (pb * 128 + tid) * QCAP;
                const int*   qib = qi + (pb * 128 + tid) * QCAP;
                for (int k = 0; k < n; k++) {
                    float v = qvb[k];
                    if (v < vmax) topk_ins(lv, li, tid, v, qib[k], vmax, maxslot);
                }
                cnts[pb * 128 + tid] = 0;
                vmx[tid] = vmax;
            }
        }
        CP_WAIT0();
        __syncthreads();
    }

    // ---- tail: drain last chunk's queue ----
    {
        const int pb = (nch - 1) & 1;
        if (tid < 128) {
            int n = min(cnts[pb * 128 + tid], QCAP);
            const float* qvb = qv + (pb * 128 + tid) * QCAP;
            const int*   qib = qi + (pb * 128 + tid) * QCAP;
            for (int k = 0; k < n; k++) {
                float v = qvb[k];
                if (v < vmax) topk_ins(lv, li, tid, v, qib[k], vmax, maxslot);
            }
        }
    }
    __syncthreads();

    // dump per-(query,split) top-16 approx candidates
    if (tid < 128) {
        int q = qt * QTILE + tid;
        int base = (q * NSPLIT + split) * KNB;
        #pragma unroll
        for (int j = 0; j < 16; j++) {
            g_topd[base + j] = lv[j * 128 + tid];
            g_topi[base + j] = li[j * 128 + tid];
        }
    }
}

// -------- kernel 3: merge 144 approx -> top-32 -> exact fp32 refine -> vote --------
__global__ void finalize_kernel(const float* __restrict__ x,
                                const float* __restrict__ train,
                                const int* __restrict__ labels,
                                float* __restrict__ pred_out,
                                float* __restrict__ proba_out) {
    __shared__ float xs[8][128];
    int warp = threadIdx.x >> 5, lane = threadIdx.x & 31;
    int q = blockIdx.x * 8 + warp;

    float cv[5]; int ci[5];
    const float* td = g_topd + (size_t)q * NCAND;
    const int*   ti = g_topi + (size_t)q * NCAND;
    #pragma unroll
    for (int t = 0; t < 5; t++) {
        int idx = lane + 32 * t;
        if (idx < NCAND) { cv[t] = td[idx]; ci[t] = ti[idx]; }
        else             { cv[t] = FLT_MAX; ci[t] = 0; }
    }

    // approx-top-32; winner of round r kept by lane r
    int myidx = 0;
    for (int r = 0; r < 32; r++) {
        float mv = cv[0]; int ms = 0;
        #pragma unroll
        for (int t = 1; t < 5; t++) if (cv[t] < mv) { mv = cv[t]; ms = t; }
        float rv = mv; int ridx = ci[0]; int rlane = lane;
        #pragma unroll
        for (int t = 0; t < 5; t++) if (t == ms) ridx = ci[t];
        #pragma unroll
        for (int o = 16; o > 0; o >>= 1) {
            float ov = __shfl_down_sync(0xffffffffu, rv, o);
            int   oi = __shfl_down_sync(0xffffffffu, ridx, o);
            int   ol = __shfl_down_sync(0xffffffffu, rlane, o);
            if (ov < rv) { rv = ov; ridx = oi; rlane = ol; }
        }
        ridx  = __shfl_sync(0xffffffffu, ridx, 0);
        rlane = __shfl_sync(0xffffffffu, rlane, 0);
        if (lane == r) myidx = ridx;
        #pragma unroll
        for (int t = 0; t < 5; t++)
            if (lane == rlane && t == ms) cv[t] = FLT_MAX;
    }

    // exact fp32 distance for my candidate
    ((float4*)xs[warp])[lane] = ((const float4*)(x + (size_t)q * DIMS))[lane];
    __syncwarp();
    const float4* t4 = (const float4*)(train + (size_t)myidx * DIMS);
    const float4* x4 = (const float4*)xs[warp];
    float dot = 0.f;
    #pragma unroll 8
    for (int i = 0; i < 32; i++) {
        float4 tv = t4[i], xv = x4[i];
        dot += xv.x*tv.x + xv.y*tv.y + xv.z*tv.z + xv.w*tv.w;
    }
    float d2 = g_x2[q] + g_t2[myidx] - 2.0f * dot;
    float myv = sqrtf(fmaxf(d2, 0.0f));
    int   lab = labels[myidx];

    // exact top-16 of 32 + weighted vote
    float proba[NC], pz[NC];
    #pragma unroll
    for (int c = 0; c < NC; c++) { proba[c] = 0.f; pz[c] = 0.f; }
    bool anyz = false;

    for (int r = 0; r < KNB; r++) {
        float rv = myv; int rlab = lab; int rlane = lane;
        #pragma unroll
        for (int o = 16; o > 0; o >>= 1) {
            float ov = __shfl_down_sync(0xffffffffu, rv, o);
            int   oi = __shfl_down_sync(0xffffffffu, rlab, o);
            int   ol = __shfl_down_sync(0xffffffffu, rlane, o);
            if (ov < rv) { rv = ov; rlab = oi; rlane = ol; }
        }
        rv    = __shfl_sync(0xffffffffu, rv, 0);
        rlab  = __shfl_sync(0xffffffffu, rlab, 0);
        rlane = __shfl_sync(0xffffffffu, rlane, 0);
        if (lane == rlane) myv = FLT_MAX;

        if (rv <= 0.0f) {
            anyz = true;
            #pragma unroll
            for (int c = 0; c < NC; c++) pz[c] += (rlab == c) ? 1.0f : 0.0f;
        } else {
            float w = 1.0f / rv;
            #pragma unroll
            for (int c = 0; c < NC; c++) proba[c] += (rlab == c) ? w : 0.0f;
        }
    }

    if (anyz) {
        #pragma unroll
        for (int c = 0; c < NC; c++) proba[c] = pz[c];
    }
    float ssum = 0.f;
    #pragma unroll
    for (int c = 0; c < NC; c++) ssum += proba[c];
    if (ssum == 0.f) ssum = 1.f;
    float inv = 1.f / ssum;

    int best = 0; float bv = proba[0];
    #pragma unroll
    for (int c = 1; c < NC; c++) if (proba[c] > bv) { bv = proba[c]; best = c; }

    if (lane == 0) {
        if (pred_out)  pred_out[q] = (float)best;
        if (proba_out) {
            #pragma unroll
            for (int c = 0; c < NC; c++) proba_out[q * NC + c] = proba[c] * inv;
        }
    }
}

// -------- launch --------
extern "C" void kernel_launch(void* const* d_in, const int* in_sizes, int n_in,
                              void* d_out, int out_size) {
    const float* x      = (const float*)d_in[0];
    const float* train  = (const float*)d_in[1];
    const int*   labels = (const int*)d_in[2];
    float* out = (float*)d_out;

    float* pred_out  = nullptr;
    float* proba_out = nullptr;
    if (out_size >= NQ * (NC + 1)) { pred_out = out; proba_out = out + NQ; }
    else if (out_size == NQ * NC)  { proba_out = out; }
    else                           { pred_out = out; }

    cudaFuncSetAttribute(knn_kernel, cudaFuncAttributeMaxDynamicSharedMemorySize, SMEM_TOTAL);

    prep_kernel<<<(MTRAIN + NQ + 128 + 7) / 8, 256>>>(x, train);
    knn_kernel<<<dim3(NSPLIT, NQ / QTILE), 256, SMEM_TOTAL>>>();
    finalize_kernel<<<NQ / 8, 256>>>(x, train, labels, pred_out, proba_out);
}